// round 17
// baseline (speedup 1.0000x reference)
#include <cuda_runtime.h>
#include <cuda_bf16.h>

#define BN 32
#define BPI0 16
#define BPI1 8
#define BPI2 4
#define NB0 (BN * BPI0)        // 512
#define NB1 (BN * BPI1)        // 256
#define NB2 (BN * BPI2)        // 128
#define NBLK (NB0 + NB1 + NB2) // 896

__device__ float g_part[NBLK * 5];
__device__ unsigned g_count = 0;

__device__ __forceinline__ float warp_sum(float v) {
    #pragma unroll
    for (int o = 16; o > 0; o >>= 1) v += __shfl_down_sync(0xffffffffu, v, o);
    return v;
}

// HW tanh (1 MUFU); sigmoid sums recovered algebraically at commit.
__device__ __forceinline__ float htanh(float x) {
    float t;
    asm("tanh.approx.f32 %0, %1;" : "=f"(t) : "f"(0.5f * x));
    return t;
}

struct Acc { float c, s, inter, z, ps; };

__device__ __forceinline__ Acc tconv(float T1, float T2, float TI,
                                     int ci, int si, float n) {
    Acc o;
    o.ps    = fmaf(0.5f, T1, 0.5f * n);
    o.z     = fmaf(0.25f, T2, fmaf(0.5f, T1, 0.25f * n));
    o.inter = fmaf(0.5f, TI, 0.5f * (float)si);
    o.c = (float)ci; o.s = (float)si;
    return o;
}

__device__ __forceinline__ void commit(Acc& a, int slot, float* s_red) {
    a.c     = warp_sum(a.c);
    a.s     = warp_sum(a.s);
    a.inter = warp_sum(a.inter);
    a.z     = warp_sum(a.z);
    a.ps    = warp_sum(a.ps);
    const int wid = threadIdx.x >> 5;
    if ((threadIdx.x & 31) == 0) {
        float* r = s_red + wid * 5;
        r[0] = a.c; r[1] = a.s; r[2] = a.inter; r[3] = a.z; r[4] = a.ps;
    }
    __syncthreads();
    if (threadIdx.x == 0) {
        float o0 = 0.f, o1 = 0.f, o2 = 0.f, o3 = 0.f, o4 = 0.f;
        #pragma unroll
        for (int w = 0; w < 8; w++) {
            o0 += s_red[w * 5 + 0]; o1 += s_red[w * 5 + 1]; o2 += s_red[w * 5 + 2];
            o3 += s_red[w * 5 + 3]; o4 += s_red[w * 5 + 4];
        }
        float* g = &g_part[slot * 5];
        g[0] = o0; g[1] = o1; g[2] = o2; g[3] = o3; g[4] = o4;
    }
}

// One row of 4 pixels: integer boundary math + tanh sums.
__device__ __forceinline__ void px_row(int4 t, int4 u, int4 d, int lft, int rgt,
                                       float4 x, float& T1, float& T2, float& TI,
                                       int& ci, int& si) {
    const float t0 = htanh(x.x), t1 = htanh(x.y),
                t2 = htanh(x.z), t3 = htanh(x.w);
    T1 += (t0 + t1) + (t2 + t3);
    T2 += (t0 * t0 + t1 * t1) + (t2 * t2 + t3 * t3);
    si += (t.x + t.y) + (t.z + t.w);
    ci += (t.x & ~(u.x & d.x & lft & t.y))
        + (t.y & ~(u.y & d.y & t.x & t.z))
        + (t.z & ~(u.z & d.z & t.y & t.w))
        + (t.w & ~(u.w & d.w & t.z & rgt));
    TI += ((t.x ? t0 : 0.f) + (t.y ? t1 : 0.f))
        + ((t.z ? t2 : 0.f) + (t.w ? t3 : 0.f));
}

// ---- scale 0: warp = 16 rows x 128-col chunk; prefetch pipeline + merged edges ----
__device__ Acc do_scale0(const float* __restrict__ lg, const int* __restrict__ tg,
                         int wlocal) {
    float T1 = 0.f, T2 = 0.f, TI = 0.f;
    int ci = 0, si = 0;
    const int lane = threadIdx.x & 31;
    const int rg = wlocal >> 2, ch = wlocal & 3;
    const int rbase = rg * 16;
    const int col = ch * 128 + lane * 4;

    const int*   p  = tg + rbase * 512 + col;
    const float* lp = lg + rbase * 512 + col;

    // merged edge-load config: lane 0 loads left neighbor, lane 31 right neighbor
    const int eoff = (lane == 0) ? -1 : 4;
    const bool eact = (lane == 0 && ch > 0) || (lane == 31 && ch < 3);

    int4 tPrev = (rbase > 0) ? __ldg((const int4*)(p - 512)) : make_int4(0,0,0,0);
    int4 tCur  = __ldg((const int4*)p);
    int4 tB    = __ldg((const int4*)(p + 512));
    int4 tNext = (rbase + 2 < 512) ? __ldg((const int4*)(p + 1024)) : make_int4(0,0,0,0);

    #pragma unroll 2
    for (int i = 0; i < 8; i++) {
        const int r0 = rbase + 2 * i;
        const int4 tB2    = (r0 + 3 < 512) ? __ldg((const int4*)(p + 1536)) : make_int4(0,0,0,0);
        const int4 tNext2 = (r0 + 4 < 512) ? __ldg((const int4*)(p + 2048)) : make_int4(0,0,0,0);
        const float4 xA = __ldg((const float4*)lp);
        const float4 xB = __ldg((const float4*)(lp + 512));

        int eA = 0, eB = 0;
        if (eact) { eA = __ldg(p + eoff); eB = __ldg(p + 512 + eoff); }

        int lA = __shfl_up_sync(0xffffffffu, tCur.w, 1);
        int lB = __shfl_up_sync(0xffffffffu, tB.w, 1);
        int rA = __shfl_down_sync(0xffffffffu, tCur.x, 1);
        int rB = __shfl_down_sync(0xffffffffu, tB.x, 1);
        if (lane == 0)  { lA = eA; lB = eB; }
        if (lane == 31) { rA = eA; rB = eB; }

        px_row(tCur, tPrev, tB, lA, rA, xA, T1, T2, TI, ci, si);
        px_row(tB, tCur, tNext, lB, rB, xB, T1, T2, TI, ci, si);

        tPrev = tB; tCur = tNext; tB = tB2; tNext = tNext2;
        p += 1024; lp += 1024;
    }
    return tconv(T1, T2, TI, ci, si, 64.0f);
}

// ---- scale 1: warp = 16 s1-rows x chunk (orig stride 2); pipelined + merged edges ----
__device__ Acc do_scale1(const float* __restrict__ lg, const int* __restrict__ tg,
                         int wlocal) {
    float T1 = 0.f, T2 = 0.f, TI = 0.f;
    int ci = 0, si = 0;
    const int lane = threadIdx.x & 31;
    const int rg = wlocal >> 2, ch = wlocal & 3;
    const int rbase = rg * 16;                    // s1 row base
    const int ocol = ch * 128 + lane * 4;

    const int*   p  = tg + rbase * 1024 + ocol;
    const float* lp = lg + rbase * 256 + ch * 64 + lane * 2;

    const int eoff = (lane == 0) ? -2 : 4;
    const bool eact = (lane == 0 && ch > 0) || (lane == 31 && ch < 3);

    int4 tPrev = (rbase > 0) ? __ldg((const int4*)(p - 1024)) : make_int4(0,0,0,0);
    int4 tCur  = __ldg((const int4*)p);
    int4 tB    = __ldg((const int4*)(p + 1024));
    int4 tNext = (rbase + 2 < 256) ? __ldg((const int4*)(p + 2048)) : make_int4(0,0,0,0);

    #pragma unroll 2
    for (int i = 0; i < 8; i++) {
        const int r0 = rbase + 2 * i;
        const int4 tB2    = (r0 + 3 < 256) ? __ldg((const int4*)(p + 3072)) : make_int4(0,0,0,0);
        const int4 tNext2 = (r0 + 4 < 256) ? __ldg((const int4*)(p + 4096)) : make_int4(0,0,0,0);
        const float2 xA = __ldg((const float2*)lp);
        const float2 xB = __ldg((const float2*)(lp + 256));

        int eA = 0, eB = 0;
        if (eact) { eA = __ldg(p + eoff); eB = __ldg(p + 1024 + eoff); }

        int lA = __shfl_up_sync(0xffffffffu, tCur.z, 1);
        int lB = __shfl_up_sync(0xffffffffu, tB.z, 1);
        int rA = __shfl_down_sync(0xffffffffu, tCur.x, 1);
        int rB = __shfl_down_sync(0xffffffffu, tB.x, 1);
        if (lane == 0)  { lA = eA; lB = eB; }
        if (lane == 31) { rA = eA; rB = eB; }

        {
            const float t0 = htanh(xA.x), t1 = htanh(xA.y);
            T1 += t0 + t1; T2 += t0 * t0 + t1 * t1;
            si += tCur.x + tCur.z;
            ci += (tCur.x & ~(tPrev.x & tB.x & lA     & tCur.z))
                + (tCur.z & ~(tPrev.z & tB.z & tCur.x & rA    ));
            TI += (tCur.x ? t0 : 0.f) + (tCur.z ? t1 : 0.f);
        }
        {
            const float t0 = htanh(xB.x), t1 = htanh(xB.y);
            T1 += t0 + t1; T2 += t0 * t0 + t1 * t1;
            si += tB.x + tB.z;
            ci += (tB.x & ~(tCur.x & tNext.x & lB   & tB.z))
                + (tB.z & ~(tCur.z & tNext.z & tB.x & rB  ));
            TI += (tB.x ? t0 : 0.f) + (tB.z ? t1 : 0.f);
        }

        tPrev = tB; tCur = tNext; tB = tB2; tNext = tNext2;
        p += 2048; lp += 512;
    }
    return tconv(T1, T2, TI, ci, si, 32.0f);
}

// ---- scale 2: warp = 16 s2-rows x chunk (orig stride 4); pipelined + merged edges ----
__device__ Acc do_scale2(const float* __restrict__ lg, const int* __restrict__ tg,
                         int wlocal) {
    float T1 = 0.f, T2 = 0.f, TI = 0.f;
    int ci = 0, si = 0;
    const int lane = threadIdx.x & 31;
    const int rg = wlocal >> 2, ch = wlocal & 3;
    const int rbase = rg * 16;                    // s2 row base
    const int ocol = ch * 128 + lane * 4;

    const int*   p  = tg + rbase * 2048 + ocol;
    const float* lp = lg + rbase * 128 + ch * 32 + lane;

    const int eoff = (lane == 0) ? -4 : 4;
    const bool eact = (lane == 0 && ch > 0) || (lane == 31 && ch < 3);

    int tPrev = (rbase > 0) ? __ldg(p - 2048) : 0;
    int tCur  = __ldg(p);
    int tB    = __ldg(p + 2048);
    int tNext = (rbase + 2 < 128) ? __ldg(p + 4096) : 0;

    #pragma unroll 2
    for (int i = 0; i < 8; i++) {
        const int r0 = rbase + 2 * i;
        const int tB2    = (r0 + 3 < 128) ? __ldg(p + 6144) : 0;
        const int tNext2 = (r0 + 4 < 128) ? __ldg(p + 8192) : 0;
        const float xA = __ldg(lp);
        const float xB = __ldg(lp + 128);

        int eA = 0, eB = 0;
        if (eact) { eA = __ldg(p + eoff); eB = __ldg(p + 2048 + eoff); }

        int lA = __shfl_up_sync(0xffffffffu, tCur, 1);
        int lB = __shfl_up_sync(0xffffffffu, tB, 1);
        int rA = __shfl_down_sync(0xffffffffu, tCur, 1);
        int rB = __shfl_down_sync(0xffffffffu, tB, 1);
        if (lane == 0)  { lA = eA; lB = eB; }
        if (lane == 31) { rA = eA; rB = eB; }

        const float t0 = htanh(xA), t1 = htanh(xB);
        T1 += t0 + t1; T2 += t0 * t0 + t1 * t1;
        si += tCur + tB;
        ci += (tCur & ~(tPrev & tB    & lA & rA))
            + (tB   & ~(tCur  & tNext & lB & rB));
        TI += (tCur ? t0 : 0.f) + (tB ? t1 : 0.f);

        tPrev = tB; tCur = tNext; tB = tB2; tNext = tNext2;
        p += 4096; lp += 256;
    }
    return tconv(T1, T2, TI, ci, si, 16.0f);
}

__global__ void __launch_bounds__(256, 3)
fused_kernel(const float* __restrict__ l0,
             const float* __restrict__ l1,
             const float* __restrict__ l2,
             const int*   __restrict__ tg,
             const float* __restrict__ vm,
             float* __restrict__ out) {
    __shared__ float s_red[8 * 5];
    __shared__ bool  s_last;
    __shared__ float s_contrib[96];
    __shared__ float s_valid[BN];

    const int bid = blockIdx.x;
    const int wid = threadIdx.x >> 5;
    Acc a;
    if (bid < NB0) {
        const int img = bid >> 4;
        const int wlocal = (bid & 15) * 8 + wid;
        a = do_scale0(l0 + (size_t)img * 512 * 512, tg + (size_t)img * 512 * 512, wlocal);
    } else if (bid < NB0 + NB1) {
        const int b = bid - NB0;
        const int img = b >> 3;
        const int wlocal = (b & 7) * 8 + wid;
        a = do_scale1(l1 + (size_t)img * 256 * 256, tg + (size_t)img * 512 * 512, wlocal);
    } else {
        const int b = bid - NB0 - NB1;
        const int img = b >> 2;
        const int wlocal = (b & 3) * 8 + wid;
        a = do_scale2(l2 + (size_t)img * 128 * 128, tg + (size_t)img * 512 * 512, wlocal);
    }
    commit(a, bid, s_red);

    __syncthreads();
    if (threadIdx.x == 0) {
        __threadfence();
        unsigned r = atomicAdd(&g_count, 1u);
        s_last = (r == NBLK - 1);
    }
    __syncthreads();
    if (!s_last) return;

    const int tid = threadIdx.x;
    if (tid == 0) g_count = 0;
    if (tid < BN) s_valid[tid] = (vm[tid] >= 0.5f) ? 1.0f : 0.0f;
    __syncthreads();

    if (tid < 96) {
        const int sc  = tid >> 5;
        const int img = tid & 31;
        int base, cntb;
        if      (sc == 0) { base = img * BPI0;             cntb = BPI0; }
        else if (sc == 1) { base = NB0 + img * BPI1;       cntb = BPI1; }
        else              { base = NB0 + NB1 + img * BPI2; cntb = BPI2; }

        float C = 0.f, S = 0.f, I = 0.f, Z = 0.f, P = 0.f;
        for (int b = 0; b < cntb; b++) {
            const float* g = &g_part[(base + b) * 5];
            C += g[0]; S += g[1]; I += g[2]; Z += g[3]; P += g[4];
        }
        const float SMOOTH = 1e-5f;
        const float ws[3]     = { 1.0f / 1.75f, 0.5f / 1.75f, 0.25f / 1.75f };
        const float inv_hw[3] = { 1.0f / (512.f * 512.f), 1.0f / (256.f * 256.f), 1.0f / (128.f * 128.f) };
        float alpha = 2.0f * (1.0f - (C + SMOOTH) / (S + SMOOTH)) - 1.0f;
        alpha = fminf(alpha, 0.8f);
        const float num = Z + S - 2.0f * I + SMOOTH;
        const float den = Z + S - (1.0f + alpha) * I + SMOOTH;
        const float dou = num / den;
        const float per = (S > 0.f) ? dou : P * inv_hw[sc];
        s_contrib[tid] = ws[sc] * per * s_valid[img];
    }
    __syncthreads();
    if (tid == 0) {
        float sum = 0.f, cnt = 0.f;
        #pragma unroll
        for (int i = 0; i < 96; i++) sum += s_contrib[i];
        #pragma unroll
        for (int i = 0; i < BN; i++) cnt += s_valid[i];
        out[0] = (cnt > 0.f) ? (sum / cnt) : 0.0f;
    }
}

extern "C" void kernel_launch(void* const* d_in, const int* in_sizes, int n_in,
                              void* d_out, int out_size) {
    const float* l0 = (const float*)d_in[0];   // [8,4,512,512]
    const float* l1 = (const float*)d_in[1];   // [8,4,256,256]
    const float* l2 = (const float*)d_in[2];   // [8,4,128,128]
    const int*   tg = (const int*)d_in[3];     // [8,4,512,512]
    const float* vm = (const float*)d_in[4];   // [8,4]
    float* out = (float*)d_out;

    fused_kernel<<<NBLK, 256>>>(l0, l1, l2, tg, vm, out);
}